// round 1
// baseline (speedup 1.0000x reference)
#include <cuda_runtime.h>
#include <math.h>

#define BSZ 512
#define TIN 128
#define FDIM 64
#define UNITS 1024
#define OUT_STEPS 32
#define NG (4*UNITS)   // 4096 packed gate columns (i,f,g,o)

// Persistent state (allocation-free scratch): double-buffered h + in-place c.
__device__ float g_hA[BSZ*UNITS];
__device__ float g_hB[BSZ*UNITS];
__device__ float g_c [BSZ*UNITS];

__device__ __forceinline__ float sigm(float x) { return 1.0f / (1.0f + expf(-x)); }

// One LSTM time step, fully fused: z = x@Wk + h@Wr + b, gates, c/h update.
// Tile: 128 batches x 32 units x 4 gates. 256 threads, 8x8-ish register blocking:
// thread (tx,ty) owns 8 batches x 2 units x 4 gates = 64 accumulators.
__global__ __launch_bounds__(256, 2)
void lstm_step_kernel(const float* __restrict__ x, int x_stride,
                      const float* __restrict__ Wk,
                      const float* __restrict__ Wr,
                      const float* __restrict__ bias,
                      const float* __restrict__ h_in,
                      float* __restrict__ h_out,
                      float* __restrict__ c_st)
{
    __shared__ float sA[8][128];   // [k][batch]
    __shared__ float sW[8][128];   // [k][gate*32 + ulocal]

    const int tid = threadIdx.x;
    const int tx = tid & 15;       // unit-pair index  (0..15)
    const int ty = tid >> 4;       // batch-octet index (0..15)
    const int m0 = blockIdx.x * 128;
    const int u0 = blockIdx.y * 32;

    float acc[4][8][2];
    #pragma unroll
    for (int g = 0; g < 4; ++g)
        #pragma unroll
        for (int bi = 0; bi < 8; ++bi)
            #pragma unroll
            for (int ui = 0; ui < 2; ++ui)
                acc[g][bi][ui] = 0.0f;

    // A-tile loader indices
    const int ar = tid >> 1;            // 0..127 (batch row)
    const int ak = (tid & 1) * 4;       // 0 or 4  (k half)
    // W-tile loader indices
    const int kw   = tid >> 5;          // 0..7
    const int lane = tid & 31;          // 0..31

    // phase 0: K=UNITS over (h_in, Wr); phase 1: K=FDIM over (x, Wk)
    #pragma unroll 1
    for (int phase = 0; phase < 2; ++phase) {
        const float* Asrc = (phase == 0) ? h_in : x;
        const int    a_ld = (phase == 0) ? UNITS : x_stride;
        const float* Wsrc = (phase == 0) ? Wr : Wk;
        const int    Ktot = (phase == 0) ? UNITS : FDIM;

        for (int k0 = 0; k0 < Ktot; k0 += 8) {
            // stage A (transpose to [k][b])
            float4 av = *(const float4*)(Asrc + (size_t)(m0 + ar) * a_ld + k0 + ak);
            sA[ak + 0][ar] = av.x;
            sA[ak + 1][ar] = av.y;
            sA[ak + 2][ar] = av.z;
            sA[ak + 3][ar] = av.w;
            // stage W (4 gate segments of 32 contiguous floats)
            #pragma unroll
            for (int g = 0; g < 4; ++g)
                sW[kw][g * 32 + lane] =
                    Wsrc[(size_t)(k0 + kw) * NG + g * UNITS + u0 + lane];
            __syncthreads();

            #pragma unroll
            for (int k = 0; k < 8; ++k) {
                float4 a0 = *(const float4*)&sA[k][ty * 8];
                float4 a1 = *(const float4*)&sA[k][ty * 8 + 4];
                float a[8] = {a0.x, a0.y, a0.z, a0.w, a1.x, a1.y, a1.z, a1.w};
                float w[8];
                #pragma unroll
                for (int g = 0; g < 4; ++g) {
                    float2 wv = *(const float2*)&sW[k][g * 32 + tx * 2];
                    w[g * 2 + 0] = wv.x;
                    w[g * 2 + 1] = wv.y;
                }
                #pragma unroll
                for (int g = 0; g < 4; ++g)
                    #pragma unroll
                    for (int bi = 0; bi < 8; ++bi)
                        #pragma unroll
                        for (int ui = 0; ui < 2; ++ui)
                            acc[g][bi][ui] = fmaf(a[bi], w[g * 2 + ui], acc[g][bi][ui]);
            }
            __syncthreads();
        }
    }

    // Epilogue: gates + state update (c in place, h to the other buffer)
    #pragma unroll
    for (int bi = 0; bi < 8; ++bi) {
        const int b = m0 + ty * 8 + bi;
        #pragma unroll
        for (int ui = 0; ui < 2; ++ui) {
            const int u = u0 + tx * 2 + ui;
            const float zi = acc[0][bi][ui] + bias[0 * UNITS + u];
            const float zf = acc[1][bi][ui] + bias[1 * UNITS + u];
            const float zg = acc[2][bi][ui] + bias[2 * UNITS + u];
            const float zo = acc[3][bi][ui] + bias[3 * UNITS + u];
            const size_t idx = (size_t)b * UNITS + u;
            const float c_old = c_st[idx];
            const float c_new = sigm(zf) * c_old + sigm(zi) * tanhf(zg);
            c_st[idx]  = c_new;
            h_out[idx] = sigm(zo) * tanhf(c_new);
        }
    }
}

// pred[b,f] = bd[f] + sum_u h[b,u] * Wd[u,f]; writes out[b, step, f].
// Block: 16 batches, 256 threads = (f 0..63) x (batch-quartet 0..3).
__global__ __launch_bounds__(256)
void dense_kernel(const float* __restrict__ h,
                  const float* __restrict__ Wd,
                  const float* __restrict__ bd,
                  float* __restrict__ out, int step)
{
    __shared__ float sh[16][128];
    const int tid = threadIdx.x;
    const int f  = tid & 63;
    const int bq = tid >> 6;             // 0..3
    const int b0 = blockIdx.x * 16;

    float acc[4] = {0.f, 0.f, 0.f, 0.f};

    const int bl = tid >> 4;             // 0..15
    const int ul = (tid & 15) * 8;       // 0..120

    for (int uc = 0; uc < UNITS; uc += 128) {
        float4 v0 = *(const float4*)(h + (size_t)(b0 + bl) * UNITS + uc + ul);
        float4 v1 = *(const float4*)(h + (size_t)(b0 + bl) * UNITS + uc + ul + 4);
        *(float4*)&sh[bl][ul]     = v0;
        *(float4*)&sh[bl][ul + 4] = v1;
        __syncthreads();
        #pragma unroll 8
        for (int u = 0; u < 128; ++u) {
            float wv = Wd[(size_t)(uc + u) * FDIM + f];
            #pragma unroll
            for (int i = 0; i < 4; ++i)
                acc[i] = fmaf(sh[bq * 4 + i][u], wv, acc[i]);
        }
        __syncthreads();
    }

    #pragma unroll
    for (int i = 0; i < 4; ++i) {
        const int b = b0 + bq * 4 + i;
        out[(size_t)b * (OUT_STEPS * FDIM) + step * FDIM + f] = acc[i] + bd[f];
    }
}

extern "C" void kernel_launch(void* const* d_in, const int* in_sizes, int n_in,
                              void* d_out, int out_size)
{
    const float* inputs = (const float*)d_in[0];   // [512,128,64]
    const float* Wk     = (const float*)d_in[1];   // [64,4096]
    const float* Wr     = (const float*)d_in[2];   // [1024,4096]
    const float* bias   = (const float*)d_in[3];   // [4096]
    const float* Wd     = (const float*)d_in[4];   // [1024,64]
    const float* bd     = (const float*)d_in[5];   // [64]
    float* out = (float*)d_out;                    // [512,32,64]

    float *hA, *hB, *cS;
    cudaGetSymbolAddress((void**)&hA, g_hA);
    cudaGetSymbolAddress((void**)&hB, g_hB);
    cudaGetSymbolAddress((void**)&cS, g_c);

    cudaMemsetAsync(hA, 0, (size_t)BSZ * UNITS * sizeof(float));
    cudaMemsetAsync(cS, 0, (size_t)BSZ * UNITS * sizeof(float));

    dim3 grid(BSZ / 128, UNITS / 32);   // 4 x 32 = 128 CTAs
    dim3 blk(256);

    float* hin  = hA;
    float* hout = hB;

    // Warm-up over the input window
    for (int t = 0; t < TIN; ++t) {
        lstm_step_kernel<<<grid, blk>>>(inputs + (size_t)t * FDIM, TIN * FDIM,
                                        Wk, Wr, bias, hin, hout, cS);
        float* tmp = hin; hin = hout; hout = tmp;
    }

    // First prediction
    dense_kernel<<<BSZ / 16, 256>>>(hin, Wd, bd, out, 0);

    // Autoregressive decode (x = previous prediction, read back from out)
    for (int s = 1; s < OUT_STEPS; ++s) {
        lstm_step_kernel<<<grid, blk>>>(out + (size_t)(s - 1) * FDIM, OUT_STEPS * FDIM,
                                        Wk, Wr, bias, hin, hout, cS);
        float* tmp = hin; hin = hout; hout = tmp;
        dense_kernel<<<BSZ / 16, 256>>>(hin, Wd, bd, out, s);
    }
}

// round 3
// speedup vs baseline: 2.0276x; 2.0276x over previous
#include <cuda_runtime.h>
#include <cuda_bf16.h>
#include <stdint.h>
#include <math.h>

#define BSZ 512
#define TIN 128
#define FDIM 64
#define UNITS 1024
#define OUT_STEPS 32
#define NGATE 4096           // 4*UNITS, gate-interleaved: n' = u*4 + g
#define KTOT 1088            // 1024 (h) + 64 (x)
#define KCHUNK 32
#define NCHUNK 34            // 32 h-chunks + 2 x-chunks

// ---------------- persistent device scratch (allocation-free) ----------------
__device__ __nv_bfloat16 g_Wt_hi[(size_t)NGATE * KTOT];  // [n'][k], K-major
__device__ __nv_bfloat16 g_Wt_lo[(size_t)NGATE * KTOT];
__device__ float         g_b2[NGATE];                    // bias reordered to n'
__device__ __nv_bfloat16 g_in_hi[(size_t)BSZ * TIN * FDIM];
__device__ __nv_bfloat16 g_in_lo[(size_t)BSZ * TIN * FDIM];
__device__ __nv_bfloat16 g_hA_hi[(size_t)BSZ * UNITS];
__device__ __nv_bfloat16 g_hA_lo[(size_t)BSZ * UNITS];
__device__ __nv_bfloat16 g_hB_hi[(size_t)BSZ * UNITS];
__device__ __nv_bfloat16 g_hB_lo[(size_t)BSZ * UNITS];
__device__ float         g_hf32[(size_t)BSZ * UNITS];
__device__ float         g_c[(size_t)BSZ * UNITS];
__device__ __nv_bfloat16 g_xd_hi[(size_t)BSZ * FDIM];
__device__ __nv_bfloat16 g_xd_lo[(size_t)BSZ * FDIM];

__device__ __forceinline__ uint32_t smem_u32(const void* p) {
    uint32_t a;
    asm("{ .reg .u64 t; cvta.to.shared.u64 t, %1; cvt.u32.u64 %0, t; }" : "=r"(a) : "l"(p));
    return a;
}
__device__ __forceinline__ void cp16(uint32_t saddr, const void* g) {
    asm volatile("cp.async.cg.shared.global [%0], [%1], 16;" :: "r"(saddr), "l"(g));
}
__device__ __forceinline__ void cp_commit() {
    asm volatile("cp.async.commit_group;" ::: "memory");
}
template <int N>
__device__ __forceinline__ void cp_wait() {
    asm volatile("cp.async.wait_group %0;" :: "n"(N) : "memory");
}

// mma.sync m16n8k16 row.col bf16 -> f32 (baseline PTX, no arch suffix)
__device__ __forceinline__ void mma16816(float* d, const uint32_t* a, const uint32_t* b) {
    asm volatile(
        "mma.sync.aligned.m16n8k16.row.col.f32.bf16.bf16.f32 "
        "{%0,%1,%2,%3}, {%4,%5,%6,%7}, {%8,%9}, {%0,%1,%2,%3};"
        : "+f"(d[0]), "+f"(d[1]), "+f"(d[2]), "+f"(d[3])
        : "r"(a[0]), "r"(a[1]), "r"(a[2]), "r"(a[3]), "r"(b[0]), "r"(b[1]));
}

__device__ __forceinline__ float sigm(float x) { return 1.0f / (1.0f + expf(-x)); }

// ---------------- SMEM layout ----------------
// [0,512): bias (128 floats). [512, 512+2*40960): two stages of 4 tiles.
// Tile = 128 rows x 32 bf16 cols, padded row stride 40 bf16 (80 bytes).
// Stage tiles: Ah(+0) Al(+10240) Bh(+20480) Bl(+30720).
// Epilogue reuses stage area as z scratch: 128 x 132 floats (67584 B).
#define TILE_B 10240
#define STAGE_B (4 * TILE_B)
#define SM_STG 512
#define SM_TOTAL (SM_STG + 2 * STAGE_B)   // 82432

__global__ __launch_bounds__(256)
void lstm_tc_kernel(const __nv_bfloat16* __restrict__ x_hi,
                    const __nv_bfloat16* __restrict__ x_lo, int x_stride,
                    const __nv_bfloat16* __restrict__ h_hi,
                    const __nv_bfloat16* __restrict__ h_lo,
                    __nv_bfloat16* __restrict__ ho_hi,
                    __nv_bfloat16* __restrict__ ho_lo,
                    float* __restrict__ hf32,
                    float* __restrict__ c_st)
{
    extern __shared__ char smem[];
    const uint32_t sbase = smem_u32(smem);
    const int tid = threadIdx.x, wid = tid >> 5, lane = tid & 31;
    const int warp_m = wid >> 2;            // 0..1 -> rows warp_m*64
    const int warp_n = wid & 3;             // 0..3 -> cols warp_n*32
    const int m0 = blockIdx.x * 128;        // batch tile
    const int u0 = blockIdx.y * 32;         // unit tile
    const int n0 = u0 * 4;                  // gate-interleaved column base

    if (tid < 128) ((float*)smem)[tid] = g_b2[n0 + tid];

    const __nv_bfloat16* __restrict__ Bh = g_Wt_hi + (size_t)n0 * KTOT;
    const __nv_bfloat16* __restrict__ Bl = g_Wt_lo + (size_t)n0 * KTOT;

    // per-thread loader indices (2 uint4 per tile per chunk)
    const int ld_row0 = tid >> 2;                 // idx = tid
    const int ld_cq0  = tid & 3;
    const int ld_row1 = (256 + tid) >> 2;         // idx = 256 + tid
    const int ld_cq1  = tid & 3;                  // (256+tid)&3 == tid&3

    // issue loads for chunk c into stage st
    auto issue = [&](int c, int st) {
        const __nv_bfloat16 *ah, *al;
        int lda;
        if (c < 32) {
            ah = h_hi + (size_t)m0 * UNITS + c * KCHUNK;
            al = h_lo + (size_t)m0 * UNITS + c * KCHUNK;
            lda = UNITS;
        } else {
            ah = x_hi + (size_t)m0 * x_stride + (c - 32) * KCHUNK;
            al = x_lo + (size_t)m0 * x_stride + (c - 32) * KCHUNK;
            lda = x_stride;
        }
        const __nv_bfloat16* bh = Bh + c * KCHUNK;
        const __nv_bfloat16* bl = Bl + c * KCHUNK;
        const uint32_t sb = sbase + SM_STG + st * STAGE_B;
        {
            const uint32_t sa = sb + ld_row0 * 80 + ld_cq0 * 16;
            cp16(sa,              ah + (size_t)ld_row0 * lda  + ld_cq0 * 8);
            cp16(sa + TILE_B,     al + (size_t)ld_row0 * lda  + ld_cq0 * 8);
            cp16(sa + 2 * TILE_B, bh + (size_t)ld_row0 * KTOT + ld_cq0 * 8);
            cp16(sa + 3 * TILE_B, bl + (size_t)ld_row0 * KTOT + ld_cq0 * 8);
        }
        {
            const uint32_t sa = sb + ld_row1 * 80 + ld_cq1 * 16;
            cp16(sa,              ah + (size_t)ld_row1 * lda  + ld_cq1 * 8);
            cp16(sa + TILE_B,     al + (size_t)ld_row1 * lda  + ld_cq1 * 8);
            cp16(sa + 2 * TILE_B, bh + (size_t)ld_row1 * KTOT + ld_cq1 * 8);
            cp16(sa + 3 * TILE_B, bl + (size_t)ld_row1 * KTOT + ld_cq1 * 8);
        }
        cp_commit();
    };

    float acc[4][4][4];   // [m-frag][n-frag][reg]
    #pragma unroll
    for (int i = 0; i < 4; ++i)
        #pragma unroll
        for (int j = 0; j < 4; ++j)
            #pragma unroll
            for (int r = 0; r < 4; ++r) acc[i][j][r] = 0.f;

    const int gr  = lane >> 2;          // 0..7
    const int gc4 = (lane & 3) * 4;     // byte offset of bf16 pair within k16

    issue(0, 0);

    for (int c = 0; c < NCHUNK; ++c) {
        const int st = c & 1;
        if (c + 1 < NCHUNK) { issue(c + 1, st ^ 1); cp_wait<1>(); }
        else                { cp_wait<0>(); }
        __syncthreads();

        const char* sb = smem + SM_STG + st * STAGE_B;
        #pragma unroll
        for (int k16 = 0; k16 < 2; ++k16) {
            const int kb = k16 * 32;   // 16 bf16 = 32 bytes
            uint32_t ah[4][4], al[4][4], bh[4][2], bl[4][2];
            #pragma unroll
            for (int mf = 0; mf < 4; ++mf) {
                const int o = (warp_m * 64 + mf * 16 + gr) * 80 + kb + gc4;
                ah[mf][0] = *(const uint32_t*)(sb + o);
                ah[mf][1] = *(const uint32_t*)(sb + o + 8 * 80);
                ah[mf][2] = *(const uint32_t*)(sb + o + 16);
                ah[mf][3] = *(const uint32_t*)(sb + o + 8 * 80 + 16);
                al[mf][0] = *(const uint32_t*)(sb + TILE_B + o);
                al[mf][1] = *(const uint32_t*)(sb + TILE_B + o + 8 * 80);
                al[mf][2] = *(const uint32_t*)(sb + TILE_B + o + 16);
                al[mf][3] = *(const uint32_t*)(sb + TILE_B + o + 8 * 80 + 16);
            }
            #pragma unroll
            for (int nf = 0; nf < 4; ++nf) {
                const int o = (warp_n * 32 + nf * 8 + gr) * 80 + kb + gc4;
                bh[nf][0] = *(const uint32_t*)(sb + 2 * TILE_B + o);
                bh[nf][1] = *(const uint32_t*)(sb + 2 * TILE_B + o + 16);
                bl[nf][0] = *(const uint32_t*)(sb + 3 * TILE_B + o);
                bl[nf][1] = *(const uint32_t*)(sb + 3 * TILE_B + o + 16);
            }
            #pragma unroll
            for (int mf = 0; mf < 4; ++mf)
                #pragma unroll
                for (int nf = 0; nf < 4; ++nf) {
                    mma16816(acc[mf][nf], ah[mf], bh[nf]);
                    mma16816(acc[mf][nf], ah[mf], bl[nf]);
                    mma16816(acc[mf][nf], al[mf], bh[nf]);
                }
        }
        __syncthreads();
    }

    // ---- epilogue: z tile -> SMEM scratch, remap, gates, state update ----
    float* zs = (float*)(smem + SM_STG);   // 128 x 132 floats
    {
        const int gcn = (lane & 3) * 2;
        #pragma unroll
        for (int mf = 0; mf < 4; ++mf)
            #pragma unroll
            for (int nf = 0; nf < 4; ++nf) {
                const int row = warp_m * 64 + mf * 16 + gr;
                const int col = warp_n * 32 + nf * 8 + gcn;
                *(float2*)&zs[row * 132 + col]       = make_float2(acc[mf][nf][0], acc[mf][nf][1]);
                *(float2*)&zs[(row + 8) * 132 + col] = make_float2(acc[mf][nf][2], acc[mf][nf][3]);
            }
    }
    __syncthreads();

    {
        const int m = tid >> 1;                 // 0..127
        const int ub = (tid & 1) * 16;          // local unit base: 0 or 16
        const float4* zrow = (const float4*)&zs[m * 132];
        const float4* bias4 = (const float4*)smem;
        const size_t idx0 = (size_t)(m0 + m) * UNITS + u0 + ub;
        #pragma unroll 4
        for (int j = 0; j < 16; ++j) {
            const int ul = ub + j;
            const float4 z4 = zrow[ul];
            const float4 bb = bias4[ul];
            const float zi = z4.x + bb.x;
            const float zf = z4.y + bb.y;
            const float zg = z4.z + bb.z;
            const float zo = z4.w + bb.w;
            const float cn = sigm(zf) * c_st[idx0 + j] + sigm(zi) * tanhf(zg);
            c_st[idx0 + j] = cn;
            const float h = sigm(zo) * tanhf(cn);
            hf32[idx0 + j] = h;
            const __nv_bfloat16 hhi = __float2bfloat16(h);
            ho_hi[idx0 + j] = hhi;
            ho_lo[idx0 + j] = __float2bfloat16(h - __bfloat162float(hhi));
        }
    }
}

// ---------------- preprocessing ----------------
__global__ void prep_weights(const float* __restrict__ Wk, const float* __restrict__ Wr,
                             const float* __restrict__ b) {
    const size_t idx = (size_t)blockIdx.x * blockDim.x + threadIdx.x;
    if (idx < (size_t)NGATE * KTOT) {
        const int n = (int)(idx / KTOT), k = (int)(idx % KTOT);
        const int u = n >> 2, g = n & 3;
        const float v = (k < UNITS) ? Wr[(size_t)k * NGATE + g * UNITS + u]
                                    : Wk[(size_t)(k - UNITS) * NGATE + g * UNITS + u];
        const __nv_bfloat16 hi = __float2bfloat16(v);
        g_Wt_hi[idx] = hi;
        g_Wt_lo[idx] = __float2bfloat16(v - __bfloat162float(hi));
    }
    if (idx < NGATE) g_b2[idx] = b[(idx & 3) * UNITS + (idx >> 2)];
}

__global__ void prep_inputs(const float* __restrict__ inp) {
    const size_t idx = (size_t)blockIdx.x * blockDim.x + threadIdx.x;
    if (idx < (size_t)BSZ * TIN * FDIM) {
        const float v = inp[idx];
        const __nv_bfloat16 hi = __float2bfloat16(v);
        g_in_hi[idx] = hi;
        g_in_lo[idx] = __float2bfloat16(v - __bfloat162float(hi));
    }
}

// ---------------- dense head ----------------
__global__ __launch_bounds__(256)
void dense_kernel(const float* __restrict__ h, const float* __restrict__ Wd,
                  const float* __restrict__ bd, float* __restrict__ out, int step) {
    __shared__ float sh[16][128];
    const int tid = threadIdx.x;
    const int f = tid & 63;
    const int bq = tid >> 6;
    const int b0 = blockIdx.x * 16;
    float acc[4] = {0.f, 0.f, 0.f, 0.f};
    const int bl = tid >> 4;
    const int ul = (tid & 15) * 8;
    for (int uc = 0; uc < UNITS; uc += 128) {
        float4 v0 = *(const float4*)(h + (size_t)(b0 + bl) * UNITS + uc + ul);
        float4 v1 = *(const float4*)(h + (size_t)(b0 + bl) * UNITS + uc + ul + 4);
        *(float4*)&sh[bl][ul] = v0;
        *(float4*)&sh[bl][ul + 4] = v1;
        __syncthreads();
        #pragma unroll 8
        for (int u = 0; u < 128; ++u) {
            const float wv = Wd[(size_t)(uc + u) * FDIM + f];
            #pragma unroll
            for (int i = 0; i < 4; ++i) acc[i] = fmaf(sh[bq * 4 + i][u], wv, acc[i]);
        }
        __syncthreads();
    }
    #pragma unroll
    for (int i = 0; i < 4; ++i) {
        const int b = b0 + bq * 4 + i;
        const float p = acc[i] + bd[f];
        out[(size_t)b * (OUT_STEPS * FDIM) + (size_t)step * FDIM + f] = p;
        const __nv_bfloat16 hi = __float2bfloat16(p);
        g_xd_hi[(size_t)b * FDIM + f] = hi;
        g_xd_lo[(size_t)b * FDIM + f] = __float2bfloat16(p - __bfloat162float(hi));
    }
}

// ---------------- launch ----------------
extern "C" void kernel_launch(void* const* d_in, const int* in_sizes, int n_in,
                              void* d_out, int out_size)
{
    const float* inputs = (const float*)d_in[0];   // [512,128,64]
    const float* Wk     = (const float*)d_in[1];   // [64,4096]
    const float* Wr     = (const float*)d_in[2];   // [1024,4096]
    const float* bias   = (const float*)d_in[3];   // [4096]
    const float* Wd     = (const float*)d_in[4];   // [1024,64]
    const float* bd     = (const float*)d_in[5];   // [64]
    float* out = (float*)d_out;                    // [512,32,64]

    static bool attr_done = false;
    if (!attr_done) {
        cudaFuncSetAttribute(lstm_tc_kernel, cudaFuncAttributeMaxDynamicSharedMemorySize, SM_TOTAL);
        attr_done = true;
    }

    __nv_bfloat16 *hAh, *hAl, *hBh, *hBl, *inh, *inl, *xdh, *xdl;
    float *hf, *cs;
    cudaGetSymbolAddress((void**)&hAh, g_hA_hi);
    cudaGetSymbolAddress((void**)&hAl, g_hA_lo);
    cudaGetSymbolAddress((void**)&hBh, g_hB_hi);
    cudaGetSymbolAddress((void**)&hBl, g_hB_lo);
    cudaGetSymbolAddress((void**)&inh, g_in_hi);
    cudaGetSymbolAddress((void**)&inl, g_in_lo);
    cudaGetSymbolAddress((void**)&xdh, g_xd_hi);
    cudaGetSymbolAddress((void**)&xdl, g_xd_lo);
    cudaGetSymbolAddress((void**)&hf, g_hf32);
    cudaGetSymbolAddress((void**)&cs, g_c);

    {
        const size_t nw = (size_t)NGATE * KTOT;
        prep_weights<<<(unsigned)((nw + 255) / 256), 256>>>(Wk, Wr, bias);
        const size_t ni = (size_t)BSZ * TIN * FDIM;
        prep_inputs<<<(unsigned)((ni + 255) / 256), 256>>>(inputs);
    }
    cudaMemsetAsync(hAh, 0, (size_t)BSZ * UNITS * sizeof(__nv_bfloat16));
    cudaMemsetAsync(hAl, 0, (size_t)BSZ * UNITS * sizeof(__nv_bfloat16));
    cudaMemsetAsync(cs, 0, (size_t)BSZ * UNITS * sizeof(float));

    const dim3 grid(BSZ / 128, UNITS / 32);  // 4 x 32 = 128 CTAs
    const dim3 blk(256);

    __nv_bfloat16 *cih = hAh, *cil = hAl, *coh = hBh, *col = hBl;

    for (int t = 0; t < TIN; ++t) {
        lstm_tc_kernel<<<grid, blk, SM_TOTAL>>>(
            inh + (size_t)t * FDIM, inl + (size_t)t * FDIM, TIN * FDIM,
            cih, cil, coh, col, hf, cs);
        __nv_bfloat16* t1 = cih; cih = coh; coh = t1;
        __nv_bfloat16* t2 = cil; cil = col; col = t2;
    }

    dense_kernel<<<BSZ / 16, 256>>>(hf, Wd, bd, out, 0);

    for (int s = 1; s < OUT_STEPS; ++s) {
        lstm_tc_kernel<<<grid, blk, SM_TOTAL>>>(
            xdh, xdl, FDIM, cih, cil, coh, col, hf, cs);
        __nv_bfloat16* t1 = cih; cih = coh; coh = t1;
        __nv_bfloat16* t2 = cil; cil = col; col = t2;
        dense_kernel<<<BSZ / 16, 256>>>(hf, Wd, bd, out, s);
    }
}

// round 4
// speedup vs baseline: 2.9125x; 1.4365x over previous
#include <cuda_runtime.h>
#include <cuda_bf16.h>
#include <stdint.h>
#include <math.h>

#define BSZ 512
#define TIN 128
#define FDIM 64
#define UNITS 1024
#define OUT_STEPS 32
#define NGATE 4096           // 4*UNITS, gate-interleaved: n' = u*4 + g
#define KTOT 1088            // 1024 (h) + 64 (x)
#define KCHUNK 64
#define NCHUNK 17            // 16 h-chunks + 1 x-chunk

// ---------------- persistent device scratch (allocation-free) ----------------
__device__ __nv_bfloat16 g_Wt_hi[(size_t)NGATE * KTOT];  // [n'][k], K-major
__device__ __nv_bfloat16 g_Wt_lo[(size_t)NGATE * KTOT];
__device__ float         g_b2[NGATE];                    // bias reordered to n'
__device__ __nv_bfloat16 g_in_hi[(size_t)BSZ * TIN * FDIM];
__device__ __nv_bfloat16 g_in_lo[(size_t)BSZ * TIN * FDIM];
__device__ __nv_bfloat16 g_hA_hi[(size_t)BSZ * UNITS];
__device__ __nv_bfloat16 g_hA_lo[(size_t)BSZ * UNITS];
__device__ __nv_bfloat16 g_hB_hi[(size_t)BSZ * UNITS];
__device__ __nv_bfloat16 g_hB_lo[(size_t)BSZ * UNITS];
__device__ float         g_hf32[(size_t)BSZ * UNITS];
__device__ float         g_c[(size_t)BSZ * UNITS];
__device__ __nv_bfloat16 g_xd_hi[(size_t)BSZ * FDIM];
__device__ __nv_bfloat16 g_xd_lo[(size_t)BSZ * FDIM];

__device__ __forceinline__ uint32_t smem_u32(const void* p) {
    uint32_t a;
    asm("{ .reg .u64 t; cvta.to.shared.u64 t, %1; cvt.u32.u64 %0, t; }" : "=r"(a) : "l"(p));
    return a;
}
__device__ __forceinline__ void cp16(uint32_t saddr, const void* g) {
    asm volatile("cp.async.cg.shared.global [%0], [%1], 16;" :: "r"(saddr), "l"(g));
}
__device__ __forceinline__ void cp_commit() {
    asm volatile("cp.async.commit_group;" ::: "memory");
}
template <int N>
__device__ __forceinline__ void cp_wait() {
    asm volatile("cp.async.wait_group %0;" :: "n"(N) : "memory");
}
__device__ __forceinline__ void ldm4(uint32_t* r, uint32_t addr) {
    asm volatile("ldmatrix.sync.aligned.m8n8.x4.shared.b16 {%0,%1,%2,%3}, [%4];"
        : "=r"(r[0]), "=r"(r[1]), "=r"(r[2]), "=r"(r[3]) : "r"(addr));
}
// mma.sync m16n8k16 row.col bf16 -> f32 (baseline PTX)
__device__ __forceinline__ void mma16816(float* d, const uint32_t* a, const uint32_t* b) {
    asm volatile(
        "mma.sync.aligned.m16n8k16.row.col.f32.bf16.bf16.f32 "
        "{%0,%1,%2,%3}, {%4,%5,%6,%7}, {%8,%9}, {%0,%1,%2,%3};"
        : "+f"(d[0]), "+f"(d[1]), "+f"(d[2]), "+f"(d[3])
        : "r"(a[0]), "r"(a[1]), "r"(a[2]), "r"(a[3]), "r"(b[0]), "r"(b[1]));
}

__device__ __forceinline__ float sigm(float x) { return 1.0f / (1.0f + expf(-x)); }

// SW128 swizzle for 128-byte rows (Swizzle<3,4,3>)
#define SWZ(o) ((o) ^ (((o) >> 3) & 0x70))

// ---------------- SMEM layout ----------------
// [0,512): bias (128 floats).
// Stage (48 KB): Ah(64x128B)=8K @0, Al @8192, Bh(128x128B)=16K @16384, Bl @32768.
// Two stages at SM_STG + st*49152. Epilogue reuses stage0 as z scratch 64x132 f32.
#define A_TILE_B 8192
#define B_TILE_B 16384
#define STAGE_B 49152
#define SM_STG 512
#define SM_TOTAL (SM_STG + 2 * STAGE_B)   // 98816

__global__ __launch_bounds__(256, 2)
void lstm_tc_kernel(const __nv_bfloat16* __restrict__ x_hi,
                    const __nv_bfloat16* __restrict__ x_lo, int x_stride,
                    const __nv_bfloat16* __restrict__ h_hi,
                    const __nv_bfloat16* __restrict__ h_lo,
                    __nv_bfloat16* __restrict__ ho_hi,
                    __nv_bfloat16* __restrict__ ho_lo,
                    float* __restrict__ hf32,
                    float* __restrict__ c_st)
{
    extern __shared__ char smem[];
    const uint32_t sbase = smem_u32(smem);
    const int tid = threadIdx.x, wid = tid >> 5, lane = tid & 31;
    const int warp_m = wid >> 2;            // 0..1 -> rows warp_m*32
    const int warp_n = wid & 3;             // 0..3 -> cols warp_n*32
    const int m0 = blockIdx.x * 64;         // batch tile (M=64)
    const int n0 = blockIdx.y * 128;        // gate-interleaved column base (N=128)
    const int u0 = blockIdx.y * 32;

    if (tid < 128) ((float*)smem)[tid] = g_b2[n0 + tid];

    const __nv_bfloat16* __restrict__ Bh = g_Wt_hi + (size_t)n0 * KTOT;
    const __nv_bfloat16* __restrict__ Bl = g_Wt_lo + (size_t)n0 * KTOT;

    // loader: per tile-chunk each thread moves 16B pieces; row = idx>>3, ch = idx&7
    auto issue = [&](int c, int st) {
        const __nv_bfloat16 *ah, *al;
        int lda;
        if (c < 16) {
            ah = h_hi + (size_t)m0 * UNITS + c * KCHUNK;
            al = h_lo + (size_t)m0 * UNITS + c * KCHUNK;
            lda = UNITS;
        } else {
            ah = x_hi + (size_t)m0 * x_stride;
            al = x_lo + (size_t)m0 * x_stride;
            lda = x_stride;
        }
        const uint32_t sb = sbase + SM_STG + st * STAGE_B;
        #pragma unroll
        for (int i = 0; i < 2; ++i) {        // A tiles: 64 rows x 8 chunks = 512
            const int idx = i * 256 + tid;
            const int row = idx >> 3, ch = idx & 7;
            const uint32_t so = SWZ(row * 128 + ch * 16);
            cp16(sb + so,            ah + (size_t)row * lda + ch * 8);
            cp16(sb + A_TILE_B + so, al + (size_t)row * lda + ch * 8);
        }
        #pragma unroll
        for (int i = 0; i < 4; ++i) {        // B tiles: 128 rows x 8 chunks = 1024
            const int idx = i * 256 + tid;
            const int row = idx >> 3, ch = idx & 7;
            const uint32_t so = SWZ(row * 128 + ch * 16);
            const size_t go = (size_t)row * KTOT + c * KCHUNK + ch * 8;
            cp16(sb + 2 * A_TILE_B + so,            Bh + go);
            cp16(sb + 2 * A_TILE_B + B_TILE_B + so, Bl + go);
        }
        cp_commit();
    };

    float acc[2][4][4];
    #pragma unroll
    for (int i = 0; i < 2; ++i)
        #pragma unroll
        for (int j = 0; j < 4; ++j)
            #pragma unroll
            for (int r = 0; r < 4; ++r) acc[i][j][r] = 0.f;

    // ldmatrix lane-relative address components (within a tile, 128B rows)
    const int a_r  = warp_m * 32 + (lane & 15);     // + mf*16 at use
    const int a_cs = (lane >> 4) * 16;              // k-half select (bytes)
    const int b_r  = warp_n * 32 + (lane & 7) + ((lane >> 4) << 3);  // + npair*16
    const int b_cs = ((lane >> 3) & 1) * 16;

    issue(0, 0);

    for (int c = 0; c < NCHUNK; ++c) {
        const int st = c & 1;
        if (c + 1 < NCHUNK) { issue(c + 1, st ^ 1); cp_wait<1>(); }
        else                { cp_wait<0>(); }
        __syncthreads();

        const uint32_t sb = sbase + SM_STG + st * STAGE_B;
        #pragma unroll
        for (int k16 = 0; k16 < 4; ++k16) {
            const int kb = k16 * 32;   // byte offset of k16 within 128B row
            uint32_t ah[2][4], al[2][4], bh[2][4], bl[2][4];
            #pragma unroll
            for (int mf = 0; mf < 2; ++mf) {
                const uint32_t so = SWZ((a_r + mf * 16) * 128 + kb + a_cs);
                ldm4(ah[mf], sb + so);
                ldm4(al[mf], sb + A_TILE_B + so);
            }
            #pragma unroll
            for (int p = 0; p < 2; ++p) {
                const uint32_t so = SWZ((b_r + p * 16) * 128 + kb + b_cs);
                ldm4(bh[p], sb + 2 * A_TILE_B + so);
                ldm4(bl[p], sb + 2 * A_TILE_B + B_TILE_B + so);
            }
            // pass-ordered: independent accumulators back-to-back
            #pragma unroll
            for (int mf = 0; mf < 2; ++mf)
                #pragma unroll
                for (int nf = 0; nf < 4; ++nf)
                    mma16816(acc[mf][nf], ah[mf], &bh[nf >> 1][(nf & 1) * 2]);
            #pragma unroll
            for (int mf = 0; mf < 2; ++mf)
                #pragma unroll
                for (int nf = 0; nf < 4; ++nf)
                    mma16816(acc[mf][nf], ah[mf], &bl[nf >> 1][(nf & 1) * 2]);
            #pragma unroll
            for (int mf = 0; mf < 2; ++mf)
                #pragma unroll
                for (int nf = 0; nf < 4; ++nf)
                    mma16816(acc[mf][nf], al[mf], &bh[nf >> 1][(nf & 1) * 2]);
        }
        __syncthreads();
    }

    // ---- epilogue: z tile -> SMEM scratch, gates, state update ----
    float* zs = (float*)(smem + SM_STG);   // 64 x 132 floats
    {
        const int gr = lane >> 2, gcn = (lane & 3) * 2;
        #pragma unroll
        for (int mf = 0; mf < 2; ++mf)
            #pragma unroll
            for (int nf = 0; nf < 4; ++nf) {
                const int row = warp_m * 32 + mf * 16 + gr;
                const int col = warp_n * 32 + nf * 8 + gcn;
                *(float2*)&zs[row * 132 + col]       = make_float2(acc[mf][nf][0], acc[mf][nf][1]);
                *(float2*)&zs[(row + 8) * 132 + col] = make_float2(acc[mf][nf][2], acc[mf][nf][3]);
            }
    }
    __syncthreads();

    {
        const int m  = tid >> 2;            // 0..63
        const int ub = (tid & 3) * 8;       // local unit base
        const float4* zrow  = (const float4*)&zs[m * 132];
        const float4* bias4 = (const float4*)smem;
        const size_t idx0 = (size_t)(m0 + m) * UNITS + u0 + ub;
        __align__(16) float cf[8], hfv[8];
        __align__(16) __nv_bfloat16 hh[8], hl[8];
        *(float4*)&cf[0] = *(const float4*)(c_st + idx0);
        *(float4*)&cf[4] = *(const float4*)(c_st + idx0 + 4);
        #pragma unroll
        for (int j = 0; j < 8; ++j) {
            const int ul = ub + j;
            const float4 z4 = zrow[ul];
            const float4 bb = bias4[ul];
            const float zi = z4.x + bb.x;
            const float zf = z4.y + bb.y;
            const float zg = z4.z + bb.z;
            const float zo = z4.w + bb.w;
            const float cn = sigm(zf) * cf[j] + sigm(zi) * tanhf(zg);
            cf[j] = cn;
            const float h = sigm(zo) * tanhf(cn);
            hfv[j] = h;
            const __nv_bfloat16 hhi = __float2bfloat16(h);
            hh[j] = hhi;
            hl[j] = __float2bfloat16(h - __bfloat162float(hhi));
        }
        *(float4*)(c_st + idx0)      = *(const float4*)&cf[0];
        *(float4*)(c_st + idx0 + 4)  = *(const float4*)&cf[4];
        *(float4*)(hf32 + idx0)      = *(const float4*)&hfv[0];
        *(float4*)(hf32 + idx0 + 4)  = *(const float4*)&hfv[4];
        *(uint4*)(ho_hi + idx0) = *(const uint4*)&hh[0];
        *(uint4*)(ho_lo + idx0) = *(const uint4*)&hl[0];
    }
}

// ---------------- preprocessing ----------------
__global__ void prep_weights(const float* __restrict__ Wk, const float* __restrict__ Wr,
                             const float* __restrict__ b) {
    const size_t idx = (size_t)blockIdx.x * blockDim.x + threadIdx.x;
    if (idx < (size_t)NGATE * KTOT) {
        const int n = (int)(idx / KTOT), k = (int)(idx % KTOT);
        const int u = n >> 2, g = n & 3;
        const float v = (k < UNITS) ? Wr[(size_t)k * NGATE + g * UNITS + u]
                                    : Wk[(size_t)(k - UNITS) * NGATE + g * UNITS + u];
        const __nv_bfloat16 hi = __float2bfloat16(v);
        g_Wt_hi[idx] = hi;
        g_Wt_lo[idx] = __float2bfloat16(v - __bfloat162float(hi));
    }
    if (idx < NGATE) g_b2[idx] = b[(idx & 3) * UNITS + (idx >> 2)];
}

__global__ void prep_inputs(const float* __restrict__ inp) {
    const size_t idx = (size_t)blockIdx.x * blockDim.x + threadIdx.x;
    if (idx < (size_t)BSZ * TIN * FDIM) {
        const float v = inp[idx];
        const __nv_bfloat16 hi = __float2bfloat16(v);
        g_in_hi[idx] = hi;
        g_in_lo[idx] = __float2bfloat16(v - __bfloat162float(hi));
    }
}

// ---------------- dense head ----------------
__global__ __launch_bounds__(256)
void dense_kernel(const float* __restrict__ h, const float* __restrict__ Wd,
                  const float* __restrict__ bd, float* __restrict__ out, int step) {
    __shared__ float sh[16][128];
    const int tid = threadIdx.x;
    const int f = tid & 63;
    const int bq = tid >> 6;
    const int b0 = blockIdx.x * 16;
    float acc[4] = {0.f, 0.f, 0.f, 0.f};
    const int bl = tid >> 4;
    const int ul = (tid & 15) * 8;
    for (int uc = 0; uc < UNITS; uc += 128) {
        float4 v0 = *(const float4*)(h + (size_t)(b0 + bl) * UNITS + uc + ul);
        float4 v1 = *(const float4*)(h + (size_t)(b0 + bl) * UNITS + uc + ul + 4);
        *(float4*)&sh[bl][ul] = v0;
        *(float4*)&sh[bl][ul + 4] = v1;
        __syncthreads();
        #pragma unroll 8
        for (int u = 0; u < 128; ++u) {
            const float wv = Wd[(size_t)(uc + u) * FDIM + f];
            #pragma unroll
            for (int i = 0; i < 4; ++i) acc[i] = fmaf(sh[bq * 4 + i][u], wv, acc[i]);
        }
        __syncthreads();
    }
    #pragma unroll
    for (int i = 0; i < 4; ++i) {
        const int b = b0 + bq * 4 + i;
        const float p = acc[i] + bd[f];
        out[(size_t)b * (OUT_STEPS * FDIM) + (size_t)step * FDIM + f] = p;
        const __nv_bfloat16 hi = __float2bfloat16(p);
        g_xd_hi[(size_t)b * FDIM + f] = hi;
        g_xd_lo[(size_t)b * FDIM + f] = __float2bfloat16(p - __bfloat162float(hi));
    }
}

// ---------------- launch ----------------
extern "C" void kernel_launch(void* const* d_in, const int* in_sizes, int n_in,
                              void* d_out, int out_size)
{
    const float* inputs = (const float*)d_in[0];
    const float* Wk     = (const float*)d_in[1];
    const float* Wr     = (const float*)d_in[2];
    const float* bias   = (const float*)d_in[3];
    const float* Wd     = (const float*)d_in[4];
    const float* bd     = (const float*)d_in[5];
    float* out = (float*)d_out;

    static bool attr_done = false;
    if (!attr_done) {
        cudaFuncSetAttribute(lstm_tc_kernel, cudaFuncAttributeMaxDynamicSharedMemorySize, SM_TOTAL);
        attr_done = true;
    }

    __nv_bfloat16 *hAh, *hAl, *hBh, *hBl, *inh, *inl, *xdh, *xdl;
    float *hf, *cs;
    cudaGetSymbolAddress((void**)&hAh, g_hA_hi);
    cudaGetSymbolAddress((void**)&hAl, g_hA_lo);
    cudaGetSymbolAddress((void**)&hBh, g_hB_hi);
    cudaGetSymbolAddress((void**)&hBl, g_hB_lo);
    cudaGetSymbolAddress((void**)&inh, g_in_hi);
    cudaGetSymbolAddress((void**)&inl, g_in_lo);
    cudaGetSymbolAddress((void**)&xdh, g_xd_hi);
    cudaGetSymbolAddress((void**)&xdl, g_xd_lo);
    cudaGetSymbolAddress((void**)&hf, g_hf32);
    cudaGetSymbolAddress((void**)&cs, g_c);

    {
        const size_t nw = (size_t)NGATE * KTOT;
        prep_weights<<<(unsigned)((nw + 255) / 256), 256>>>(Wk, Wr, bias);
        const size_t ni = (size_t)BSZ * TIN * FDIM;
        prep_inputs<<<(unsigned)((ni + 255) / 256), 256>>>(inputs);
    }
    cudaMemsetAsync(hAh, 0, (size_t)BSZ * UNITS * sizeof(__nv_bfloat16));
    cudaMemsetAsync(hAl, 0, (size_t)BSZ * UNITS * sizeof(__nv_bfloat16));
    cudaMemsetAsync(cs, 0, (size_t)BSZ * UNITS * sizeof(float));

    const dim3 grid(BSZ / 64, NGATE / 128);  // 8 x 32 = 256 CTAs
    const dim3 blk(256);

    __nv_bfloat16 *cih = hAh, *cil = hAl, *coh = hBh, *col = hBl;

    for (int t = 0; t < TIN; ++t) {
        lstm_tc_kernel<<<grid, blk, SM_TOTAL>>>(
            inh + (size_t)t * FDIM, inl + (size_t)t * FDIM, TIN * FDIM,
            cih, cil, coh, col, hf, cs);
        __nv_bfloat16* t1 = cih; cih = coh; coh = t1;
        __nv_bfloat16* t2 = cil; cil = col; col = t2;
    }

    dense_kernel<<<BSZ / 16, 256>>>(hf, Wd, bd, out, 0);

    for (int s = 1; s < OUT_STEPS; ++s) {
        lstm_tc_kernel<<<grid, blk, SM_TOTAL>>>(
            xdh, xdl, FDIM, cih, cil, coh, col, hf, cs);
        __nv_bfloat16* t1 = cih; cih = coh; coh = t1;
        __nv_bfloat16* t2 = cil; cil = col; col = t2;
        dense_kernel<<<BSZ / 16, 256>>>(hf, Wd, bd, out, s);
    }
}

// round 5
// speedup vs baseline: 3.0348x; 1.0420x over previous
#include <cuda_runtime.h>
#include <cuda_bf16.h>
#include <stdint.h>
#include <math.h>

#define BSZ 512
#define TIN 128
#define FDIM 64
#define UNITS 1024
#define OUT_STEPS 32
#define NSTEPS 159           // TIN + OUT_STEPS - 1 LSTM steps
#define NGATE 4096           // 4*UNITS, gate-interleaved: n' = u*4 + g
#define KTOT 1088            // 1024 (h) + 64 (x)
#define KCHUNK 64
#define NCHUNK 17            // 16 h-chunks + 1 x-chunk
#define NBLK 256

// ---------------- persistent device scratch (allocation-free) ----------------
__device__ __nv_bfloat16 g_Wt_hi[(size_t)NGATE * KTOT];  // [n'][k], K-major
__device__ __nv_bfloat16 g_Wt_lo[(size_t)NGATE * KTOT];
__device__ float         g_b2[NGATE];                    // bias reordered to n'
__device__ __nv_bfloat16 g_in_hi[(size_t)BSZ * TIN * FDIM];
__device__ __nv_bfloat16 g_in_lo[(size_t)BSZ * TIN * FDIM];
__device__ __nv_bfloat16 g_hA_hi[(size_t)BSZ * UNITS];
__device__ __nv_bfloat16 g_hA_lo[(size_t)BSZ * UNITS];
__device__ __nv_bfloat16 g_hB_hi[(size_t)BSZ * UNITS];
__device__ __nv_bfloat16 g_hB_lo[(size_t)BSZ * UNITS];
__device__ float         g_c[(size_t)BSZ * UNITS];
__device__ __nv_bfloat16 g_xd_hi[(size_t)BSZ * FDIM];
__device__ __nv_bfloat16 g_xd_lo[(size_t)BSZ * FDIM];
__device__ unsigned      g_bar[2];                       // [0]=count, [1]=generation

__device__ __forceinline__ uint32_t smem_u32(const void* p) {
    uint32_t a;
    asm("{ .reg .u64 t; cvta.to.shared.u64 t, %1; cvt.u32.u64 %0, t; }" : "=r"(a) : "l"(p));
    return a;
}
__device__ __forceinline__ void cp16(uint32_t saddr, const void* g) {
    asm volatile("cp.async.cg.shared.global [%0], [%1], 16;" :: "r"(saddr), "l"(g));
}
__device__ __forceinline__ void cp_commit() {
    asm volatile("cp.async.commit_group;" ::: "memory");
}
template <int N>
__device__ __forceinline__ void cp_wait() {
    asm volatile("cp.async.wait_group %0;" :: "n"(N) : "memory");
}
__device__ __forceinline__ void ldm4(uint32_t* r, uint32_t addr) {
    asm volatile("ldmatrix.sync.aligned.m8n8.x4.shared.b16 {%0,%1,%2,%3}, [%4];"
        : "=r"(r[0]), "=r"(r[1]), "=r"(r[2]), "=r"(r[3]) : "r"(addr));
}
__device__ __forceinline__ void mma16816(float* d, const uint32_t* a, const uint32_t* b) {
    asm volatile(
        "mma.sync.aligned.m16n8k16.row.col.f32.bf16.bf16.f32 "
        "{%0,%1,%2,%3}, {%4,%5,%6,%7}, {%8,%9}, {%0,%1,%2,%3};"
        : "+f"(d[0]), "+f"(d[1]), "+f"(d[2]), "+f"(d[3])
        : "r"(a[0]), "r"(a[1]), "r"(a[2]), "r"(a[3]), "r"(b[0]), "r"(b[1]));
}
__device__ __forceinline__ float sigm(float x) { return 1.0f / (1.0f + expf(-x)); }
__device__ __forceinline__ void unp2(unsigned v, float& x, float& y) {
    x = __uint_as_float(v << 16);
    y = __uint_as_float(v & 0xFFFF0000u);
}

#define SWZ(o) ((o) ^ (((o) >> 3) & 0x70))

// ---------------- SMEM layout ----------------
// [0,512): bias (128 floats).
// Stage (48 KB): Ah(64x128B)=8K @0, Al @8192, Bh(128x128B)=16K @16384, Bl @32768.
// Two stages at SM_STG + st*49152. Epilogue z scratch (64x132 f32) lives in stage 1.
#define A_TILE_B 8192
#define B_TILE_B 16384
#define STAGE_B 49152
#define SM_STG 512
#define SM_TOTAL (SM_STG + 2 * STAGE_B)   // 98816

__device__ __forceinline__ void grid_barrier(unsigned target) {
    __threadfence();
    __syncthreads();
    if (threadIdx.x == 0) {
        if (atomicAdd(&g_bar[0], 1u) == NBLK - 1u) {
            atomicExch(&g_bar[0], 0u);
            __threadfence();
            atomicExch(&g_bar[1], target);
        } else {
            while (((volatile unsigned*)g_bar)[1] < target) __nanosleep(64);
            __threadfence();
        }
    }
    __syncthreads();
}

__global__ __launch_bounds__(256, 2)
void lstm_persist(const float* __restrict__ Wd,
                  const float* __restrict__ bd,
                  float* __restrict__ out)
{
    extern __shared__ char smem[];
    const uint32_t sbase = smem_u32(smem);
    const int tid = threadIdx.x, wid = tid >> 5, lane = tid & 31;
    const int warp_m = wid >> 2;            // 0..1 -> rows warp_m*32
    const int warp_n = wid & 3;             // 0..3 -> cols warp_n*32
    const int m0 = blockIdx.x * 64;         // batch tile (M=64)
    const int n0 = blockIdx.y * 128;        // gate-interleaved column base (N=128)
    const int u0 = blockIdx.y * 32;
    const int flat = blockIdx.y * gridDim.x + blockIdx.x;

    if (tid < 128) ((float*)smem)[tid] = g_b2[n0 + tid];

    const __nv_bfloat16* __restrict__ Bh = g_Wt_hi + (size_t)n0 * KTOT;
    const __nv_bfloat16* __restrict__ Bl = g_Wt_lo + (size_t)n0 * KTOT;

    // ldmatrix lane-relative address components
    const int a_r  = warp_m * 32 + (lane & 15);
    const int a_cs = (lane >> 4) * 16;
    const int b_r  = warp_n * 32 + (lane & 7) + ((lane >> 4) << 3);
    const int b_cs = ((lane >> 3) & 1) * 16;

    unsigned lgen = 0;

    // W loader (weights are step-invariant)
    auto issueW = [&](int c, int st) {
        const uint32_t sb = sbase + SM_STG + st * STAGE_B + 2 * A_TILE_B;
        #pragma unroll
        for (int i = 0; i < 4; ++i) {
            const int idx = i * 256 + tid;
            const int row = idx >> 3, ch = idx & 7;
            const uint32_t so = SWZ(row * 128 + ch * 16);
            const size_t go = (size_t)row * KTOT + c * KCHUNK + ch * 8;
            cp16(sb + so,            Bh + go);
            cp16(sb + B_TILE_B + so, Bl + go);
        }
    };

    #pragma unroll 1
    for (int t = 0; t < NSTEPS; ++t) {
        const __nv_bfloat16* hih = (t & 1) ? g_hB_hi : g_hA_hi;
        const __nv_bfloat16* hil = (t & 1) ? g_hB_lo : g_hA_lo;
        __nv_bfloat16* hoh = (t & 1) ? g_hA_hi : g_hB_hi;
        __nv_bfloat16* hol = (t & 1) ? g_hA_lo : g_hB_lo;
        const __nv_bfloat16 *xh, *xl;
        int xstride;
        if (t < TIN) { xh = g_in_hi + (size_t)t * FDIM; xl = g_in_lo + (size_t)t * FDIM; xstride = TIN * FDIM; }
        else         { xh = g_xd_hi; xl = g_xd_lo; xstride = FDIM; }

        auto issueA = [&](int c, int st) {
            const __nv_bfloat16 *ah, *al;
            int lda;
            if (c < 16) {
                ah = hih + (size_t)m0 * UNITS + c * KCHUNK;
                al = hil + (size_t)m0 * UNITS + c * KCHUNK;
                lda = UNITS;
            } else {
                ah = xh + (size_t)m0 * xstride;
                al = xl + (size_t)m0 * xstride;
                lda = xstride;
            }
            const uint32_t sb = sbase + SM_STG + st * STAGE_B;
            #pragma unroll
            for (int i = 0; i < 2; ++i) {
                const int idx = i * 256 + tid;
                const int row = idx >> 3, ch = idx & 7;
                const uint32_t so = SWZ(row * 128 + ch * 16);
                cp16(sb + so,            ah + (size_t)row * lda + ch * 8);
                cp16(sb + A_TILE_B + so, al + (size_t)row * lda + ch * 8);
            }
        };

        int c0;
        if (t == 0) { c0 = 16; issueA(16, 0); issueW(16, 0); cp_commit(); }
        else        { c0 = 0;  issueA(0, 0);  cp_commit(); }   // W0 pre-issued last step

        float acc[2][4][4];
        #pragma unroll
        for (int i = 0; i < 2; ++i)
            #pragma unroll
            for (int j = 0; j < 4; ++j)
                #pragma unroll
                for (int r = 0; r < 4; ++r) acc[i][j][r] = 0.f;

        #pragma unroll 1
        for (int c = c0; c < NCHUNK; ++c) {
            const int st = c & 1;
            cp_wait<0>();
            __syncthreads();
            if (c + 1 < NCHUNK) { issueA(c + 1, st ^ 1); issueW(c + 1, st ^ 1); cp_commit(); }

            const uint32_t sb = sbase + SM_STG + st * STAGE_B;
            #pragma unroll
            for (int k16 = 0; k16 < 4; ++k16) {
                const int kb = k16 * 32;
                uint32_t ah[2][4], al[2][4], bh[2][4], bl[2][4];
                #pragma unroll
                for (int mf = 0; mf < 2; ++mf) {
                    const uint32_t so = SWZ((a_r + mf * 16) * 128 + kb + a_cs);
                    ldm4(ah[mf], sb + so);
                    ldm4(al[mf], sb + A_TILE_B + so);
                }
                #pragma unroll
                for (int p = 0; p < 2; ++p) {
                    const uint32_t so = SWZ((b_r + p * 16) * 128 + kb + b_cs);
                    ldm4(bh[p], sb + 2 * A_TILE_B + so);
                    ldm4(bl[p], sb + 2 * A_TILE_B + B_TILE_B + so);
                }
                #pragma unroll
                for (int mf = 0; mf < 2; ++mf)
                    #pragma unroll
                    for (int nf = 0; nf < 4; ++nf)
                        mma16816(acc[mf][nf], ah[mf], &bh[nf >> 1][(nf & 1) * 2]);
                #pragma unroll
                for (int mf = 0; mf < 2; ++mf)
                    #pragma unroll
                    for (int nf = 0; nf < 4; ++nf)
                        mma16816(acc[mf][nf], ah[mf], &bl[nf >> 1][(nf & 1) * 2]);
                #pragma unroll
                for (int mf = 0; mf < 2; ++mf)
                    #pragma unroll
                    for (int nf = 0; nf < 4; ++nf)
                        mma16816(acc[mf][nf], al[mf], &bh[nf >> 1][(nf & 1) * 2]);
            }
        }

        // ---- epilogue (z scratch in stage 1) ----
        float* zs = (float*)(smem + SM_STG + STAGE_B);
        {
            const int gr = lane >> 2, gcn = (lane & 3) * 2;
            __syncthreads();   // all warps done with compute(16) before stage-1 reuse
            #pragma unroll
            for (int mf = 0; mf < 2; ++mf)
                #pragma unroll
                for (int nf = 0; nf < 4; ++nf) {
                    const int row = warp_m * 32 + mf * 16 + gr;
                    const int col = warp_n * 32 + nf * 8 + gcn;
                    *(float2*)&zs[row * 132 + col]       = make_float2(acc[mf][nf][0], acc[mf][nf][1]);
                    *(float2*)&zs[(row + 8) * 132 + col] = make_float2(acc[mf][nf][2], acc[mf][nf][3]);
                }
        }
        __syncthreads();
        {
            const int m  = tid >> 2;
            const int ub = (tid & 3) * 8;
            const float4* zrow  = (const float4*)&zs[m * 132];
            const float4* bias4 = (const float4*)smem;
            const size_t idx0 = (size_t)(m0 + m) * UNITS + u0 + ub;
            __align__(16) float cf[8];
            __align__(16) __nv_bfloat16 hh[8], hl[8];
            if (t == 0) {
                #pragma unroll
                for (int j = 0; j < 8; ++j) cf[j] = 0.f;
            } else {
                *(float4*)&cf[0] = *(const float4*)(g_c + idx0);
                *(float4*)&cf[4] = *(const float4*)(g_c + idx0 + 4);
            }
            #pragma unroll
            for (int j = 0; j < 8; ++j) {
                const int ul = ub + j;
                const float4 z4 = zrow[ul];
                const float4 bb = bias4[ul];
                const float zi = z4.x + bb.x;
                const float zf = z4.y + bb.y;
                const float zg = z4.z + bb.z;
                const float zo = z4.w + bb.w;
                const float cn = sigm(zf) * cf[j] + sigm(zi) * tanhf(zg);
                cf[j] = cn;
                const float h = sigm(zo) * tanhf(cn);
                const __nv_bfloat16 hhi = __float2bfloat16(h);
                hh[j] = hhi;
                hl[j] = __float2bfloat16(h - __bfloat162float(hhi));
            }
            *(float4*)(g_c + idx0)     = *(const float4*)&cf[0];
            *(float4*)(g_c + idx0 + 4) = *(const float4*)&cf[4];
            *(uint4*)(hoh + idx0) = *(const uint4*)&hh[0];
            *(uint4*)(hol + idx0) = *(const uint4*)&hl[0];
        }

        if (t + 1 < NSTEPS) { issueW(0, 0); cp_commit(); }   // prefetch next step's W0 across the barrier
        grid_barrier(++lgen);

        if (t >= TIN - 1) {
            const int ds = t - (TIN - 1);
            if (flat < 64) {
                const int bg = flat >> 3;
                const int fg = flat & 7;
                const int bl_ = tid >> 2;
                const int f0 = fg * 8 + (tid & 3);
                const int b  = bg * 64 + bl_;
                const uint2* hhp = (const uint2*)(hoh + (size_t)b * UNITS);
                const uint2* hlp = (const uint2*)(hol + (size_t)b * UNITS);
                float a0 = 0.f, a1 = 0.f;
                #pragma unroll 4
                for (int kq = 0; kq < UNITS / 4; ++kq) {
                    const uint2 vh = __ldcg(hhp + kq);
                    const uint2 vl = __ldcg(hlp + kq);
                    float h0, h1, h2, h3, l0, l1, l2, l3;
                    unp2(vh.x, h0, h1); unp2(vh.y, h2, h3);
                    unp2(vl.x, l0, l1); unp2(vl.y, l2, l3);
                    const float hv0 = h0 + l0, hv1 = h1 + l1, hv2 = h2 + l2, hv3 = h3 + l3;
                    const float* w = Wd + (size_t)kq * 4 * FDIM;
                    a0 = fmaf(hv0, w[f0], a0);            a1 = fmaf(hv0, w[f0 + 4], a1);
                    a0 = fmaf(hv1, w[64 + f0], a0);       a1 = fmaf(hv1, w[64 + f0 + 4], a1);
                    a0 = fmaf(hv2, w[128 + f0], a0);      a1 = fmaf(hv2, w[128 + f0 + 4], a1);
                    a0 = fmaf(hv3, w[192 + f0], a0);      a1 = fmaf(hv3, w[192 + f0 + 4], a1);
                }
                const float p0 = a0 + bd[f0];
                const float p1 = a1 + bd[f0 + 4];
                out[(size_t)b * (OUT_STEPS * FDIM) + (size_t)ds * FDIM + f0]     = p0;
                out[(size_t)b * (OUT_STEPS * FDIM) + (size_t)ds * FDIM + f0 + 4] = p1;
                const __nv_bfloat16 p0h = __float2bfloat16(p0);
                const __nv_bfloat16 p1h = __float2bfloat16(p1);
                g_xd_hi[(size_t)b * FDIM + f0]     = p0h;
                g_xd_hi[(size_t)b * FDIM + f0 + 4] = p1h;
                g_xd_lo[(size_t)b * FDIM + f0]     = __float2bfloat16(p0 - __bfloat162float(p0h));
                g_xd_lo[(size_t)b * FDIM + f0 + 4] = __float2bfloat16(p1 - __bfloat162float(p1h));
            }
            if (t + 1 < NSTEPS) grid_barrier(++lgen);
        }
    }
}

// ---------------- preprocessing: coalesced tiled transpose ----------------
__global__ __launch_bounds__(256)
void prep_weights(const float* __restrict__ Wk, const float* __restrict__ Wr,
                  const float* __restrict__ b) {
    __shared__ float tile[64][65];            // [n'_loc][k_loc]
    const int k0 = blockIdx.x * 64;           // k base (17 blocks)
    const int u0 = blockIdx.y * 16;           // u base (64 blocks)
    const int r  = threadIdx.x >> 2;          // k row local 0..63
    const int cq = threadIdx.x & 3;           // u quad
    const int k  = k0 + r;
    #pragma unroll
    for (int g = 0; g < 4; ++g) {
        const int col = g * UNITS + u0 + cq * 4;
        float4 v;
        if (k < UNITS) v = *(const float4*)(Wr + (size_t)k * NGATE + col);
        else           v = *(const float4*)(Wk + (size_t)(k - UNITS) * NGATE + col);
        tile[(cq * 4 + 0) * 4 + g][r] = v.x;
        tile[(cq * 4 + 1) * 4 + g][r] = v.y;
        tile[(cq * 4 + 2) * 4 + g][r] = v.z;
        tile[(cq * 4 + 3) * 4 + g][r] = v.w;
    }
    if (blockIdx.x == 0 && blockIdx.y == 0)
        for (int i = threadIdx.x; i < NGATE; i += 256)
            g_b2[i] = b[(i & 3) * UNITS + (i >> 2)];
    __syncthreads();
    const int nl = threadIdx.x >> 2;          // n' local 0..63
    const int kk = (threadIdx.x & 3) * 16;    // k sub-chunk
    const size_t ng = (size_t)(blockIdx.y * 64 + nl);
    __align__(16) __nv_bfloat16 hb[16], lb[16];
    #pragma unroll
    for (int j = 0; j < 16; ++j) {
        const float v = tile[nl][kk + j];
        const __nv_bfloat16 hi = __float2bfloat16(v);
        hb[j] = hi;
        lb[j] = __float2bfloat16(v - __bfloat162float(hi));
    }
    *(uint4*)(g_Wt_hi + ng * KTOT + k0 + kk)     = *(const uint4*)&hb[0];
    *(uint4*)(g_Wt_hi + ng * KTOT + k0 + kk + 8) = *(const uint4*)&hb[8];
    *(uint4*)(g_Wt_lo + ng * KTOT + k0 + kk)     = *(const uint4*)&lb[0];
    *(uint4*)(g_Wt_lo + ng * KTOT + k0 + kk + 8) = *(const uint4*)&lb[8];
}

__global__ void prep_inputs(const float* __restrict__ inp) {
    const size_t idx = (size_t)blockIdx.x * blockDim.x + threadIdx.x;
    if (idx < (size_t)BSZ * TIN * FDIM) {
        const float v = inp[idx];
        const __nv_bfloat16 hi = __float2bfloat16(v);
        g_in_hi[idx] = hi;
        g_in_lo[idx] = __float2bfloat16(v - __bfloat162float(hi));
    }
}

// ---------------- launch ----------------
extern "C" void kernel_launch(void* const* d_in, const int* in_sizes, int n_in,
                              void* d_out, int out_size)
{
    const float* inputs = (const float*)d_in[0];
    const float* Wk     = (const float*)d_in[1];
    const float* Wr     = (const float*)d_in[2];
    const float* bias   = (const float*)d_in[3];
    const float* Wd     = (const float*)d_in[4];
    const float* bd     = (const float*)d_in[5];
    float* out = (float*)d_out;

    static bool attr_done = false;
    if (!attr_done) {
        cudaFuncSetAttribute(lstm_persist, cudaFuncAttributeMaxDynamicSharedMemorySize, SM_TOTAL);
        attr_done = true;
    }

    void* bar_addr;
    cudaGetSymbolAddress(&bar_addr, g_bar);
    cudaMemsetAsync(bar_addr, 0, 2 * sizeof(unsigned));

    prep_weights<<<dim3(17, 64), 256>>>(Wk, Wr, bias);
    {
        const size_t ni = (size_t)BSZ * TIN * FDIM;
        prep_inputs<<<(unsigned)((ni + 255) / 256), 256>>>(inputs);
    }

    lstm_persist<<<dim3(BSZ / 64, NGATE / 128), 256, SM_TOTAL>>>(Wd, bd, out);
}